// round 4
// baseline (speedup 1.0000x reference)
#include <cuda_runtime.h>
#include <cuda_bf16.h>
#include <cstdint>

// ---------------- problem constants ----------------
#define NT 4096          // tokens
#define KF 1024          // in_feat
#define OF 4096          // out_feat
#define NE 8             // experts

// ---------------- tiling ----------------
#define BM 128
#define BN 128
#define BK 32
#define MAX_MT (NT / BM + NE)       // 40 padded M tiles max
#define PERM_SZ (MAX_MT * BM)       // 5120
#define NK (KF / BK)                // 32 k-iterations
#define ASTRIDE 36                  // floats per smem row (conflict-free, 16B aligned)
#define BUF_FLOATS (BM * ASTRIDE)   // 4608 floats per tile buffer
#define B_OFF (2 * BUF_FLOATS)      // B buffers start after A double buffer
#define SMEM_BYTES (4 * BUF_FLOATS * 4)  // 73728 bytes

// ---------------- scratch (no allocations allowed) ----------------
__device__ int g_perm[PERM_SZ];
__device__ int g_tile_expert[MAX_MT];

// ---------------- fused dispatch (single block) ----------------
// init perm -> histogram -> prefix/tile-map -> scatter, one kernel.
__global__ void k_dispatch(const int* __restrict__ gate) {
    __shared__ int s_cnt[NE];
    __shared__ int s_off[NE];
    __shared__ int s_cur[NE];
    const int t = threadIdx.x;

    // init
    for (int i = t; i < PERM_SZ; i += 256) g_perm[i] = -1;
    if (t < NE) { s_cnt[t] = 0; s_cur[t] = 0; }
    __syncthreads();

    // histogram
    for (int n = t; n < NT; n += 256) atomicAdd(&s_cnt[gate[n]], 1);
    __syncthreads();

    // prefix + tile->expert map
    if (t == 0) {
        int off = 0;
        for (int e = 0; e < NE; e++) {
            s_off[e] = off;
            int ntile = (s_cnt[e] + BM - 1) / BM;
            int t0 = off / BM;
            for (int i = 0; i < ntile; i++) g_tile_expert[t0 + i] = e;
            off += ntile * BM;
        }
        for (int i = off / BM; i < MAX_MT; i++) g_tile_expert[i] = -1;
    }
    __syncthreads();

    // scatter
    for (int n = t; n < NT; n += 256) {
        int e = gate[n];
        int p = atomicAdd(&s_cur[e], 1);
        g_perm[s_off[e] + p] = n;
    }
}

// ---------------- tf32 helpers ----------------
__device__ __forceinline__ uint32_t f2tf(float f) {
    uint32_t u;
    asm("cvt.rna.tf32.f32 %0, %1;" : "=r"(u) : "f"(f));
    return u;
}

#define CP_ASYNC(dst, src, sz) \
    asm volatile("cp.async.cg.shared.global [%0], [%1], 16, %2;\n" \
                 :: "r"(dst), "l"(src), "r"(sz))

// ---------------- grouped GEMM ----------------
// C[m,n] = sum_k A[perm[m], k] * W[e][n, k]   (both operands K-major -> row.col mma)
__global__ __launch_bounds__(256, 1)
void k_gemm(const float* __restrict__ inp,
            const float* __restrict__ w,
            float* __restrict__ out) {
    extern __shared__ float smem[];
    const int mt = blockIdx.x;      // mt fastest -> wave spans many M tiles, few N cols (L2 weight reuse)
    const int nt = blockIdx.y;
    const int e = g_tile_expert[mt];
    if (e < 0) return;              // empty padded tile

    const float* wbase = w + (size_t)e * OF * KF;

    const int t = threadIdx.x;
    const int warp = t >> 5, lane = t & 31;
    const int wm = warp >> 2;       // 0..1 -> 64-row warp tile
    const int wn = warp & 3;        // 0..3 -> 32-col warp tile

    // ---- per-thread load descriptors (4 rows of A + 4 rows of B per thread) ----
    const int c4 = (t & 7) * 4;     // float column offset of this thread's 16B chunk
    const float* aptr[4];
    const float* bptr[4];
    uint32_t asz[4], adst[4], bdst[4];
    uint32_t smem_u32 = (uint32_t)__cvta_generic_to_shared(smem);
#pragma unroll
    for (int i = 0; i < 4; i++) {
        int r = (t >> 3) + i * 32;
        int p = g_perm[mt * BM + r];
        aptr[i] = inp + (p >= 0 ? (size_t)p * KF : 0) + c4;
        asz[i]  = (p >= 0) ? 16u : 0u;   // src-size 0 => zero-fill pad rows
        bptr[i] = wbase + (size_t)(nt * BN + r) * KF + c4;
        adst[i] = smem_u32 + (uint32_t)((r * ASTRIDE + c4) * 4);
        bdst[i] = smem_u32 + (uint32_t)((B_OFF + r * ASTRIDE + c4) * 4);
    }

    float acc[4][4][4];
#pragma unroll
    for (int im = 0; im < 4; im++)
#pragma unroll
        for (int in = 0; in < 4; in++)
#pragma unroll
            for (int q = 0; q < 4; q++) acc[im][in][q] = 0.0f;

    auto loadk = [&](int kt, int buf) {
        int k0 = kt * BK;
        uint32_t bo = (uint32_t)(buf * BUF_FLOATS * 4);
#pragma unroll
        for (int i = 0; i < 4; i++) {
            CP_ASYNC(adst[i] + bo, aptr[i] + k0, asz[i]);
            CP_ASYNC(bdst[i] + bo, bptr[i] + k0, 16u);
        }
        asm volatile("cp.async.commit_group;\n");
    };

    auto compute = [&](int buf) {
        const float* Ab = smem + buf * BUF_FLOATS;
        const float* Bb = smem + B_OFF + buf * BUF_FLOATS;
        const int lr = lane >> 2, lc = lane & 3;
#pragma unroll
        for (int ks = 0; ks < 4; ks++) {
            const int kc = ks * 8 + lc;
            uint32_t af[4][4], bf[4][2];
#pragma unroll
            for (int im = 0; im < 4; im++) {
                int r0 = wm * 64 + im * 16 + lr;
                af[im][0] = f2tf(Ab[r0 * ASTRIDE + kc]);
                af[im][1] = f2tf(Ab[(r0 + 8) * ASTRIDE + kc]);
                af[im][2] = f2tf(Ab[r0 * ASTRIDE + kc + 4]);
                af[im][3] = f2tf(Ab[(r0 + 8) * ASTRIDE + kc + 4]);
            }
#pragma unroll
            for (int in = 0; in < 4; in++) {
                int n0 = wn * 32 + in * 8 + lr;
                bf[in][0] = f2tf(Bb[n0 * ASTRIDE + kc]);
                bf[in][1] = f2tf(Bb[n0 * ASTRIDE + kc + 4]);
            }
#pragma unroll
            for (int im = 0; im < 4; im++)
#pragma unroll
                for (int in = 0; in < 4; in++)
                    asm volatile(
                        "mma.sync.aligned.m16n8k8.row.col.f32.tf32.tf32.f32 "
                        "{%0,%1,%2,%3}, {%4,%5,%6,%7}, {%8,%9}, {%0,%1,%2,%3};\n"
                        : "+f"(acc[im][in][0]), "+f"(acc[im][in][1]),
                          "+f"(acc[im][in][2]), "+f"(acc[im][in][3])
                        : "r"(af[im][0]), "r"(af[im][1]), "r"(af[im][2]), "r"(af[im][3]),
                          "r"(bf[in][0]), "r"(bf[in][1]));
        }
    };

    // ---- pipelined mainloop (double-buffered cp.async) ----
    loadk(0, 0);
    asm volatile("cp.async.wait_group 0;\n");
    __syncthreads();

    int buf = 0;
#pragma unroll 1
    for (int kt = 0; kt < NK; kt++) {
        if (kt + 1 < NK) loadk(kt + 1, buf ^ 1);
        compute(buf);
        asm volatile("cp.async.wait_group 0;\n");
        __syncthreads();
        buf ^= 1;
    }

    // ---- epilogue: scatter rows back via perm ----
    const int lr = lane >> 2;
    const int lc2 = (lane & 3) * 2;
#pragma unroll
    for (int im = 0; im < 4; im++) {
        int rm = mt * BM + wm * 64 + im * 16 + lr;
        int p0 = g_perm[rm];
        int p1 = g_perm[rm + 8];
#pragma unroll
        for (int in = 0; in < 4; in++) {
            int cn = nt * BN + wn * 32 + in * 8 + lc2;
            if (p0 >= 0)
                *(float2*)&out[(size_t)p0 * OF + cn] =
                    make_float2(acc[im][in][0], acc[im][in][1]);
            if (p1 >= 0)
                *(float2*)&out[(size_t)p1 * OF + cn] =
                    make_float2(acc[im][in][2], acc[im][in][3]);
        }
    }
}

// ---------------- launch ----------------
extern "C" void kernel_launch(void* const* d_in, const int* in_sizes, int n_in,
                              void* d_out, int out_size) {
    const float* inp  = (const float*)d_in[0];
    const int*   gate = (const int*)d_in[1];
    const float* w    = (const float*)d_in[2];
    float* out = (float*)d_out;

    static bool attr_set = false;
    if (!attr_set) {
        cudaFuncSetAttribute(k_gemm, cudaFuncAttributeMaxDynamicSharedMemorySize, SMEM_BYTES);
        attr_set = true;
    }

    k_dispatch<<<1, 256>>>(gate);
    k_gemm<<<dim3(MAX_MT, OF / BN), 256, SMEM_BYTES>>>(inp, w, out);
}

// round 16
// speedup vs baseline: 1.3678x; 1.3678x over previous
#include <cuda_runtime.h>
#include <cuda_fp16.h>
#include <cstdint>

// ---------------- problem constants ----------------
#define NT 4096
#define KF 1024
#define OF 4096
#define NE 8

// ---------------- tiling ----------------
#define BM 128
#define BN 128
#define BKH 64                      // halves per k-tile (128B row)
#define NKT (KF / BKH)              // 16
#define MAX_MT (NT / BM + NE)       // 40
#define PERM_SZ (MAX_MT * BM)       // 5120

#define ROWB 144                    // padded smem row: 72 halves = 36 words (conflict-free)
#define TILEB (BM * ROWB)           // 18432 B
#define SMEM_BYTES (4 * TILEB)      // A0,A1,B0,B1 = 73728 B

// ---------------- scratch (no allocations allowed) ----------------
__device__ __half g_wh[(size_t)NE * OF * KF];   // 64 MB fp16 weights
__device__ __half g_ih[(size_t)NT * KF];        // 8 MB fp16 inputs
__device__ int g_perm[PERM_SZ];
__device__ int g_tile_expert[MAX_MT];

// ---------------- fp32 -> fp16 conversion (per launch, deterministic) ----------------
__global__ void k_convert(const float* __restrict__ w, const float* __restrict__ inp) {
    const size_t NW = (size_t)NE * OF * KF / 4;   // float4 count
    const size_t NI = (size_t)NT * KF / 4;
    const size_t stride = (size_t)gridDim.x * blockDim.x;
    const float4* w4 = (const float4*)w;
    const float4* i4 = (const float4*)inp;
    __half2* wo = (__half2*)g_wh;
    __half2* io = (__half2*)g_ih;
    for (size_t i = (size_t)blockIdx.x * blockDim.x + threadIdx.x; i < NW; i += stride) {
        float4 v = w4[i];
        wo[2 * i]     = __floats2half2_rn(v.x, v.y);
        wo[2 * i + 1] = __floats2half2_rn(v.z, v.w);
    }
    for (size_t i = (size_t)blockIdx.x * blockDim.x + threadIdx.x; i < NI; i += stride) {
        float4 v = i4[i];
        io[2 * i]     = __floats2half2_rn(v.x, v.y);
        io[2 * i + 1] = __floats2half2_rn(v.z, v.w);
    }
}

// ---------------- fused dispatch (single block) ----------------
__global__ void k_dispatch(const int* __restrict__ gate) {
    __shared__ int s_cnt[NE];
    __shared__ int s_off[NE];
    __shared__ int s_cur[NE];
    const int t = threadIdx.x;

    for (int i = t; i < PERM_SZ; i += 256) g_perm[i] = -1;
    if (t < NE) { s_cnt[t] = 0; s_cur[t] = 0; }
    __syncthreads();

    for (int n = t; n < NT; n += 256) atomicAdd(&s_cnt[gate[n]], 1);
    __syncthreads();

    if (t == 0) {
        int off = 0;
        for (int e = 0; e < NE; e++) {
            s_off[e] = off;
            int ntile = (s_cnt[e] + BM - 1) / BM;
            int t0 = off / BM;
            for (int i = 0; i < ntile; i++) g_tile_expert[t0 + i] = e;
            off += ntile * BM;
        }
        for (int i = off / BM; i < MAX_MT; i++) g_tile_expert[i] = -1;
    }
    __syncthreads();

    for (int n = t; n < NT; n += 256) {
        int e = gate[n];
        int p = atomicAdd(&s_cur[e], 1);
        g_perm[s_off[e] + p] = n;
    }
}

#define CP_ASYNC(dst, src, sz) \
    asm volatile("cp.async.cg.shared.global [%0], [%1], 16, %2;\n" \
                 :: "r"(dst), "l"(src), "r"(sz))

// ---------------- fp16 grouped GEMM ----------------
// C[m,n] = sum_k A[perm[m],k] * W[e][n,k]; both operands K-major in smem -> row.col mma
__global__ __launch_bounds__(512, 1)
void k_gemm(float* __restrict__ out) {
    extern __shared__ char smem[];
    const int mt = blockIdx.x;      // mt fastest -> wave shares weight tiles in L2
    const int nt = blockIdx.y;
    const int e = g_tile_expert[mt];
    if (e < 0) return;

    const int t = threadIdx.x;
    const int warp = t >> 5, lane = t & 31;
    const int wm = warp >> 2, wn = warp & 3;          // 4x4 warp grid, 32x32 warp tiles
    const int g = lane >> 2, tq = lane & 3;

    // ---- loader mapping: 4 threads/row, 2x16B chunks each ----
    const int lr = t >> 2;                 // 0..127
    const int lc = (t & 3) * 2;            // starting 16B-chunk index (0,2,4,6)
    const int pA = g_perm[mt * BM + lr];
    const __half* asrc = g_ih + (size_t)(pA >= 0 ? pA : 0) * KF + lc * 8;
    const uint32_t asz = (pA >= 0) ? 16u : 0u;        // zero-fill pad rows
    const __half* bsrc = g_wh + ((size_t)e * OF + (size_t)(nt * BN + lr)) * KF + lc * 8;

    const uint32_t sb = (uint32_t)__cvta_generic_to_shared(smem);
    const uint32_t adst = sb + lr * ROWB + lc * 16;
    const uint32_t bdst = sb + 2 * TILEB + lr * ROWB + lc * 16;

    auto load_tile = [&](int kt, int buf) {
        const uint32_t bo = (uint32_t)buf * TILEB;
        const int ko = kt * BKH;
#pragma unroll
        for (int j = 0; j < 2; j++) {
            CP_ASYNC(adst + bo + j * 16, asrc + ko + j * 8, asz);
            CP_ASYNC(bdst + bo + j * 16, bsrc + ko + j * 8, 16u);
        }
        asm volatile("cp.async.commit_group;\n" ::: "memory");
    };

    float c[2][4][4];
#pragma unroll
    for (int im = 0; im < 2; im++)
#pragma unroll
        for (int in = 0; in < 4; in++)
#pragma unroll
            for (int q = 0; q < 4; q++) c[im][in][q] = 0.0f;

    auto compute = [&](int buf) {
        const uint32_t* Ab = (const uint32_t*)(smem + (size_t)buf * TILEB);
        const uint32_t* Bb = (const uint32_t*)(smem + 2 * (size_t)TILEB + (size_t)buf * TILEB);
#pragma unroll
        for (int ks = 0; ks < 4; ks++) {
            const int kw = ks * 8 + tq;   // 32-bit word index within 36-word row
            uint32_t a[2][4];
#pragma unroll
            for (int im = 0; im < 2; im++) {
                const int r0 = wm * 32 + im * 16 + g;
                a[im][0] = Ab[r0 * 36 + kw];
                a[im][1] = Ab[(r0 + 8) * 36 + kw];
                a[im][2] = Ab[r0 * 36 + kw + 4];
                a[im][3] = Ab[(r0 + 8) * 36 + kw + 4];
            }
            uint32_t b[4][2];
#pragma unroll
            for (int in = 0; in < 4; in++) {
                const int n0 = wn * 32 + in * 8 + g;
                b[in][0] = Bb[n0 * 36 + kw];
                b[in][1] = Bb[n0 * 36 + kw + 4];
            }
#pragma unroll
            for (int im = 0; im < 2; im++)
#pragma unroll
                for (int in = 0; in < 4; in++)
                    asm volatile(
                        "mma.sync.aligned.m16n8k16.row.col.f32.f16.f16.f32 "
                        "{%0,%1,%2,%3}, {%4,%5,%6,%7}, {%8,%9}, {%0,%1,%2,%3};\n"
                        : "+f"(c[im][in][0]), "+f"(c[im][in][1]),
                          "+f"(c[im][in][2]), "+f"(c[im][in][3])
                        : "r"(a[im][0]), "r"(a[im][1]), "r"(a[im][2]), "r"(a[im][3]),
                          "r"(b[in][0]), "r"(b[in][1]));
        }
    };

    // ---- double-buffered mainloop ----
    load_tile(0, 0);
    int buf = 0;
#pragma unroll 1
    for (int kt = 0; kt < NKT; kt++) {
        if (kt + 1 < NKT) {
            load_tile(kt + 1, buf ^ 1);
            asm volatile("cp.async.wait_group 1;\n" ::: "memory");
        } else {
            asm volatile("cp.async.wait_group 0;\n" ::: "memory");
        }
        __syncthreads();
        compute(buf);
        __syncthreads();
        buf ^= 1;
    }

    // ---- epilogue: scatter via perm ----
#pragma unroll
    for (int im = 0; im < 2; im++) {
        const int m0 = mt * BM + wm * 32 + im * 16 + g;
        const int p0 = g_perm[m0];
        const int p1 = g_perm[m0 + 8];
#pragma unroll
        for (int in = 0; in < 4; in++) {
            const int cn = nt * BN + wn * 32 + in * 8 + tq * 2;
            if (p0 >= 0)
                *(float2*)&out[(size_t)p0 * OF + cn] = make_float2(c[im][in][0], c[im][in][1]);
            if (p1 >= 0)
                *(float2*)&out[(size_t)p1 * OF + cn] = make_float2(c[im][in][2], c[im][in][3]);
        }
    }
}

// ---------------- launch ----------------
extern "C" void kernel_launch(void* const* d_in, const int* in_sizes, int n_in,
                              void* d_out, int out_size) {
    const float* inp  = (const float*)d_in[0];
    const int*   gate = (const int*)d_in[1];
    const float* w    = (const float*)d_in[2];
    float* out = (float*)d_out;

    static bool attr_set = false;
    if (!attr_set) {
        cudaFuncSetAttribute(k_gemm, cudaFuncAttributeMaxDynamicSharedMemorySize, SMEM_BYTES);
        attr_set = true;
    }

    k_convert<<<4096, 256>>>(w, inp);
    k_dispatch<<<1, 256>>>(gate);
    k_gemm<<<dim3(MAX_MT, OF / BN), 512, SMEM_BYTES>>>(out);
}